// round 10
// baseline (speedup 1.0000x reference)
#include <cuda_runtime.h>
#include <math.h>
#include <stdint.h>

// Problem dims (fixed per reference setup_inputs)
#define TT   4
#define BBB  64
#define NNN  256
#define DIN  512
#define DOUT 512
#define MROWS (TT * BBB * NNN)        // 65536 rows total
#define M3   (BBB * NNN * DOUT)       // 8388608 elems per time step
#define RED_ROWS 256
#define RED_BLOCKS (MROWS / RED_ROWS) // 256
#define BK 16
#define NCHUNKS (DIN / BK)            // 32

// GEMM smem pipeline
#define STG 5
#define A_STRIDE 20                   // floats per A row (padded, 16B-aligned, bank-safe)
#define A_BYTES (128 * A_STRIDE * 4)  // 10240
#define B_BYTES (BK * 128 * 4)        // 8192
#define STAGE_BYTES (A_BYTES + B_BYTES)   // 18432
#define GEMM_SMEM (STG * STAGE_BYTES)     // 92160 B -> 2 CTAs/SM fits 228KB

// Scratch (allocation-free: __device__ globals)
__device__ float g_z[(size_t)MROWS * DOUT];
__device__ float g_Wt[DOUT * DIN];    // W transposed: Wt[d][o]
__device__ float g_psum[RED_BLOCKS * DOUT];
__device__ float g_psumsq[RED_BLOCKS * DOUT];
__device__ float g_mean[DOUT];
__device__ float g_rstd[DOUT];

__device__ __forceinline__ uint32_t smem_u32(const void* p) {
    uint32_t a;
    asm("{ .reg .u64 t; cvta.to.shared.u64 t, %1; cvt.u32.u64 %0, t; }" : "=r"(a) : "l"(p));
    return a;
}
__device__ __forceinline__ void cp16(uint32_t dst, const void* src) {
    asm volatile("cp.async.cg.shared.global [%0], [%1], 16;" :: "r"(dst), "l"(src));
}

// ---------------------------------------------------------------------------
// W transpose: Wt[d][o] = W[o][d]. Pure data movement (bit-exact values).
// ---------------------------------------------------------------------------
__global__ void transpose_w_kernel(const float* __restrict__ W) {
    __shared__ float t[32][33];
    const int bd = blockIdx.x * 32;   // d offset
    const int bo = blockIdx.y * 32;   // o offset
    const int x = threadIdx.x, y = threadIdx.y;   // 32 x 8
#pragma unroll
    for (int i = 0; i < 32; i += 8)
        t[y + i][x] = W[(size_t)(bo + y + i) * DIN + bd + x];
    __syncthreads();
#pragma unroll
    for (int i = 0; i < 32; i += 8)
        g_Wt[(size_t)(bd + y + i) * DOUT + bo + x] = t[x][y + i];
}

// ---------------------------------------------------------------------------
// SGEMM: Z[m,o] = sum_d X[m,d] * W[o,d]
// 128x128 CTA tile, BK=16, 256 threads, 8x8/thread. cp.async 5-stage ring,
// one __syncthreads per chunk. A in smem row-major [row][20], B transposed
// [kk][128] (from g_Wt). FFMA chain bit-identical to the 740us kernel:
// acc[i][j] += ra[i]*rb[j], k = 0..511 ascending, single fp32 accumulator.
// ---------------------------------------------------------------------------
__global__ __launch_bounds__(256, 2) void sgemm_kernel(const float* __restrict__ X) {
    extern __shared__ __align__(16) float sm[];
    const uint32_t sbase = smem_u32(sm);
    const int tid = threadIdx.x;
    const int tx = tid & 15;           // column group
    const int ty = tid >> 4;           // row group
    const int m0 = blockIdx.y * 128;
    const int n0 = blockIdx.x * 128;

    // load-index precompute
    const int arow = tid >> 2;         // 0..63 (A vec 0), +64 for vec 1
    const int aq = tid & 3;            // 16B slot in row
    const int bkr = tid >> 5;          // 0..7 (B vec 0), +8 for vec 1
    const int bcq = tid & 31;          // 16B slot in 128-col row
    const float* Arow0 = X + (size_t)(m0 + arow) * DIN + aq * 4;
    const float* Arow1 = Arow0 + (size_t)64 * DIN;
    const uint32_t adst0 = arow * (A_STRIDE * 4) + aq * 16;
    const uint32_t adst1 = (arow + 64) * (A_STRIDE * 4) + aq * 16;
    const float* Brow0 = g_Wt + (size_t)bkr * DOUT + n0 + bcq * 4;
    const float* Brow1 = Brow0 + (size_t)8 * DOUT;
    const uint32_t bdst0 = bkr * 512 + bcq * 16;
    const uint32_t bdst1 = (bkr + 8) * 512 + bcq * 16;

    float acc[8][8];
#pragma unroll
    for (int i = 0; i < 8; i++)
#pragma unroll
        for (int j = 0; j < 8; j++) acc[i][j] = 0.f;

    // prologue: prefetch chunks 0..2
#pragma unroll
    for (int c = 0; c < 3; c++) {
        const uint32_t st = sbase + c * STAGE_BYTES;
        const int k0 = c * BK;
        cp16(st + adst0, Arow0 + k0);
        cp16(st + adst1, Arow1 + k0);
        cp16(st + A_BYTES + bdst0, Brow0 + (size_t)k0 * DOUT);
        cp16(st + A_BYTES + bdst1, Brow1 + (size_t)k0 * DOUT);
        asm volatile("cp.async.commit_group;" ::: "memory");
    }

    int stage = 0;        // stage of chunk c
    int pstage = 3;       // stage of chunk c+3
    for (int c = 0; c < NCHUNKS; c++) {
        // issue chunk c+3 (stage (c+3)%5 — untouched by any in-flight consumer)
        if (c + 3 < NCHUNKS) {
            const uint32_t st = sbase + pstage * STAGE_BYTES;
            const int k0 = (c + 3) * BK;
            cp16(st + adst0, Arow0 + k0);
            cp16(st + adst1, Arow1 + k0);
            cp16(st + A_BYTES + bdst0, Brow0 + (size_t)k0 * DOUT);
            cp16(st + A_BYTES + bdst1, Brow1 + (size_t)k0 * DOUT);
            asm volatile("cp.async.commit_group;" ::: "memory");
        }
        // wait until chunk c's group has landed (exact pending count)
        if (c < NCHUNKS - 3)       asm volatile("cp.async.wait_group 3;" ::: "memory");
        else if (c == NCHUNKS - 3) asm volatile("cp.async.wait_group 2;" ::: "memory");
        else if (c == NCHUNKS - 2) asm volatile("cp.async.wait_group 1;" ::: "memory");
        else                       asm volatile("cp.async.wait_group 0;" ::: "memory");
        __syncthreads();

        const float* As = sm + stage * (STAGE_BYTES / 4);
        const float* Bs = As + (A_BYTES / 4);
#pragma unroll
        for (int kk = 0; kk < BK; kk++) {
            float ra[8];
#pragma unroll
            for (int i = 0; i < 4; i++) {
                ra[i]     = As[(ty * 4 + i) * A_STRIDE + kk];
                ra[4 + i] = As[(64 + ty * 4 + i) * A_STRIDE + kk];
            }
            float4 b0 = *reinterpret_cast<const float4*>(&Bs[kk * 128 + tx * 4]);
            float4 b1 = *reinterpret_cast<const float4*>(&Bs[kk * 128 + 64 + tx * 4]);
            float rb[8] = {b0.x, b0.y, b0.z, b0.w, b1.x, b1.y, b1.z, b1.w};
#pragma unroll
            for (int i = 0; i < 8; i++)
#pragma unroll
                for (int j = 0; j < 8; j++) acc[i][j] += ra[i] * rb[j];
        }
        if (++stage == STG) stage = 0;
        if (++pstage == STG) pstage = 0;
    }

    // Epilogue (same mapping as the 740us kernel)
#pragma unroll
    for (int rh = 0; rh < 2; rh++)
#pragma unroll
        for (int i = 0; i < 4; i++) {
            int row = m0 + rh * 64 + ty * 4 + i;
            float* zrow = g_z + (size_t)row * DOUT + n0;
#pragma unroll
            for (int ch = 0; ch < 2; ch++) {
                float4 v;
                v.x = acc[rh * 4 + i][ch * 4 + 0];
                v.y = acc[rh * 4 + i][ch * 4 + 1];
                v.z = acc[rh * 4 + i][ch * 4 + 2];
                v.w = acc[rh * 4 + i][ch * 4 + 3];
                *reinterpret_cast<float4*>(zrow + ch * 64 + tx * 4) = v;
            }
        }
}

// ---------------------------------------------------------------------------
// Stats + LIF: verbatim from the round-1/5 PASSING kernels.
// ---------------------------------------------------------------------------
__global__ __launch_bounds__(256) void reduce_stats_kernel() {
    const int c = threadIdx.x;
    const size_t base = (size_t)blockIdx.x * RED_ROWS * DOUT;
    float s0 = 0.f, q0 = 0.f, s1 = 0.f, q1 = 0.f;
    for (int r = 0; r < RED_ROWS; r++) {
        float z0 = g_z[base + (size_t)r * DOUT + c];
        float z1 = g_z[base + (size_t)r * DOUT + c + 256];
        s0 += z0; q0 += z0 * z0;
        s1 += z1; q1 += z1 * z1;
    }
    g_psum  [blockIdx.x * DOUT + c]       = s0;
    g_psumsq[blockIdx.x * DOUT + c]       = q0;
    g_psum  [blockIdx.x * DOUT + c + 256] = s1;
    g_psumsq[blockIdx.x * DOUT + c + 256] = q1;
}

__global__ void finalize_stats_kernel() {
    const int o = threadIdx.x;
    float s = 0.f, q = 0.f;
    for (int b = 0; b < RED_BLOCKS; b++) {
        s += g_psum[b * DOUT + o];
        q += g_psumsq[b * DOUT + o];
    }
    const float invM = 1.0f / (float)MROWS;
    float mean = s * invM;
    float var = q * invM - mean * mean;
    g_mean[o] = mean;
    g_rstd[o] = 1.0f / sqrtf(var + 1e-5f);
}

__global__ __launch_bounds__(256) void lif_kernel(const float* __restrict__ gamma,
                                                  const float* __restrict__ beta,
                                                  float* __restrict__ out) {
    size_t e = ((size_t)blockIdx.x * blockDim.x + threadIdx.x) * 4;
    int o = (int)(e & (DOUT - 1));

    float4 mn4 = *reinterpret_cast<const float4*>(g_mean + o);
    float4 rs4 = *reinterpret_cast<const float4*>(g_rstd + o);
    float4 gm4 = *reinterpret_cast<const float4*>(gamma + o);
    float4 bt4 = *reinterpret_cast<const float4*>(beta + o);
    float mn[4] = {mn4.x, mn4.y, mn4.z, mn4.w};
    float rs[4] = {rs4.x, rs4.y, rs4.z, rs4.w};
    float gm[4] = {gm4.x, gm4.y, gm4.z, gm4.w};
    float bt[4] = {bt4.x, bt4.y, bt4.z, bt4.w};

    float v[4] = {0.f, 0.f, 0.f, 0.f};
#pragma unroll
    for (int t = 0; t < TT; t++) {
        float4 z4 = *reinterpret_cast<const float4*>(g_z + (size_t)t * M3 + e);
        float z[4] = {z4.x, z4.y, z4.z, z4.w};
        float s[4];
#pragma unroll
        for (int l = 0; l < 4; l++) {
            float zn = __fadd_rn(__fmul_rn(__fmul_rn(__fsub_rn(z[l], mn[l]), rs[l]), gm[l]), bt[l]);
            v[l] = __fadd_rn(v[l], __fmul_rn(__fsub_rn(zn, v[l]), 0.5f));
            bool fire = (v[l] >= 1.0f);
            s[l] = fire ? 1.0f : 0.0f;
            v[l] = fire ? 0.0f : v[l];
        }
        *reinterpret_cast<float4*>(out + (size_t)t * M3 + e) = make_float4(s[0], s[1], s[2], s[3]);
    }
}

// ---------------------------------------------------------------------------
extern "C" void kernel_launch(void* const* d_in, const int* in_sizes, int n_in,
                              void* d_out, int out_size) {
    const float* x     = (const float*)d_in[0];
    const float* W     = (const float*)d_in[1];
    const float* gamma = (const float*)d_in[2];
    const float* beta  = (const float*)d_in[3];
    float* out = (float*)d_out;

    cudaFuncSetAttribute(sgemm_kernel, cudaFuncAttributeMaxDynamicSharedMemorySize, GEMM_SMEM);

    transpose_w_kernel<<<dim3(16, 16), dim3(32, 8)>>>(W);
    dim3 gemm_grid(DOUT / 128, MROWS / 128);     // (4, 512)
    sgemm_kernel<<<gemm_grid, 256, GEMM_SMEM>>>(x);
    reduce_stats_kernel<<<RED_BLOCKS, 256>>>();
    finalize_stats_kernel<<<1, DOUT>>>();
    lif_kernel<<<M3 / (256 * 4), 256>>>(gamma, beta, out);
}

// round 11
// speedup vs baseline: 1.0446x; 1.0446x over previous
#include <cuda_runtime.h>
#include <math.h>

// Problem dims (fixed per reference setup_inputs)
#define TT   4
#define BBB  64
#define NNN  256
#define DIN  512
#define DOUT 512
#define MROWS (TT * BBB * NNN)        // 65536 rows total
#define M3   (BBB * NNN * DOUT)       // 8388608 elems per time step
#define RED_ROWS 256
#define RED_BLOCKS (MROWS / RED_ROWS) // 256
#define BK 16
#define NCHUNKS (DIN / BK)            // 32

// Scratch (allocation-free: __device__ globals)
__device__ float g_z[(size_t)MROWS * DOUT];
__device__ float g_psum[RED_BLOCKS * DOUT];
__device__ float g_psumsq[RED_BLOCKS * DOUT];
__device__ float g_mean[DOUT];
__device__ float g_rstd[DOUT];

// ---------------------------------------------------------------------------
// SGEMM: Z[m,o] = sum_d X[m,d] * W[o,d]
// 128x128 CTA tile, BK=16, 256 threads, 8x8/thread, double-buffered SMEM,
// 2 CTAs/SM — identical structure to the round-5 740us kernel, plus register
// fragment double-buffering in the kk loop (prefetch kk+1's fragments during
// kk's FFMAs). Per-accumulator FFMA order is UNCHANGED: k = 0..511 ascending,
// single fp32 accumulator -> bit-identical output.
// ---------------------------------------------------------------------------
__global__ __launch_bounds__(256, 2) void sgemm_kernel(const float* __restrict__ X,
                                                       const float* __restrict__ W) {
    __shared__ __align__(16) float As[2][BK][128];
    __shared__ __align__(16) float Bs[2][BK][128];

    const int tid = threadIdx.x;
    const int tx = tid & 15;          // column groups
    const int ty = tid >> 4;          // row groups
    const int r0 = tid >> 2;          // load row (first half)
    const int q0 = tid & 3;           // float4 index within 16-float row chunk

    const float* Ab = X + (size_t)blockIdx.y * 128 * DIN;
    const float* Wb = W + (size_t)blockIdx.x * 128 * DIN;

    float acc[8][8];
#pragma unroll
    for (int i = 0; i < 8; i++)
#pragma unroll
        for (int j = 0; j < 8; j++) acc[i][j] = 0.f;

    float4 ra0, ra1, rb0, rb1;   // staging regs for the in-flight chunk

    // --- prologue: chunk 0 -> buf 0
    ra0 = *reinterpret_cast<const float4*>(Ab + (size_t)r0 * DIN + q0 * 4);
    ra1 = *reinterpret_cast<const float4*>(Ab + (size_t)(r0 + 64) * DIN + q0 * 4);
    rb0 = *reinterpret_cast<const float4*>(Wb + (size_t)r0 * DIN + q0 * 4);
    rb1 = *reinterpret_cast<const float4*>(Wb + (size_t)(r0 + 64) * DIN + q0 * 4);
    {
        float a0[4] = {ra0.x, ra0.y, ra0.z, ra0.w};
        float a1[4] = {ra1.x, ra1.y, ra1.z, ra1.w};
        float b0[4] = {rb0.x, rb0.y, rb0.z, rb0.w};
        float b1[4] = {rb1.x, rb1.y, rb1.z, rb1.w};
#pragma unroll
        for (int u = 0; u < 4; u++) {
            As[0][q0 * 4 + u][r0]      = a0[u];
            As[0][q0 * 4 + u][r0 + 64] = a1[u];
            Bs[0][q0 * 4 + u][r0]      = b0[u];
            Bs[0][q0 * 4 + u][r0 + 64] = b1[u];
        }
    }
    __syncthreads();

    // LDG chunk 1
    ra0 = *reinterpret_cast<const float4*>(Ab + (size_t)r0 * DIN + BK + q0 * 4);
    ra1 = *reinterpret_cast<const float4*>(Ab + (size_t)(r0 + 64) * DIN + BK + q0 * 4);
    rb0 = *reinterpret_cast<const float4*>(Wb + (size_t)r0 * DIN + BK + q0 * 4);
    rb1 = *reinterpret_cast<const float4*>(Wb + (size_t)(r0 + 64) * DIN + BK + q0 * 4);

    for (int c = 0; c < NCHUNKS; c++) {
        const int cur = c & 1;
        if (c + 1 < NCHUNKS) {
            const int nxt = cur ^ 1;
            float a0[4] = {ra0.x, ra0.y, ra0.z, ra0.w};
            float a1[4] = {ra1.x, ra1.y, ra1.z, ra1.w};
            float b0[4] = {rb0.x, rb0.y, rb0.z, rb0.w};
            float b1[4] = {rb1.x, rb1.y, rb1.z, rb1.w};
#pragma unroll
            for (int u = 0; u < 4; u++) {
                As[nxt][q0 * 4 + u][r0]      = a0[u];
                As[nxt][q0 * 4 + u][r0 + 64] = a1[u];
                Bs[nxt][q0 * 4 + u][r0]      = b0[u];
                Bs[nxt][q0 * 4 + u][r0 + 64] = b1[u];
            }
        }
        if (c + 2 < NCHUNKS) {
            const int k0 = (c + 2) * BK;
            ra0 = *reinterpret_cast<const float4*>(Ab + (size_t)r0 * DIN + k0 + q0 * 4);
            ra1 = *reinterpret_cast<const float4*>(Ab + (size_t)(r0 + 64) * DIN + k0 + q0 * 4);
            rb0 = *reinterpret_cast<const float4*>(Wb + (size_t)r0 * DIN + k0 + q0 * 4);
            rb1 = *reinterpret_cast<const float4*>(Wb + (size_t)(r0 + 64) * DIN + k0 + q0 * 4);
        }

        // Compute chunk c with register fragment double-buffering.
        {
            float4 fa0 = *reinterpret_cast<const float4*>(&As[cur][0][ty * 4]);
            float4 fa1 = *reinterpret_cast<const float4*>(&As[cur][0][64 + ty * 4]);
            float4 fb0 = *reinterpret_cast<const float4*>(&Bs[cur][0][tx * 4]);
            float4 fb1 = *reinterpret_cast<const float4*>(&Bs[cur][0][64 + tx * 4]);
#pragma unroll
            for (int kk = 0; kk < BK; kk++) {
                float4 na0, na1, nb0, nb1;
                if (kk + 1 < BK) {
                    na0 = *reinterpret_cast<const float4*>(&As[cur][kk + 1][ty * 4]);
                    na1 = *reinterpret_cast<const float4*>(&As[cur][kk + 1][64 + ty * 4]);
                    nb0 = *reinterpret_cast<const float4*>(&Bs[cur][kk + 1][tx * 4]);
                    nb1 = *reinterpret_cast<const float4*>(&Bs[cur][kk + 1][64 + tx * 4]);
                }
                float ra[8] = {fa0.x, fa0.y, fa0.z, fa0.w, fa1.x, fa1.y, fa1.z, fa1.w};
                float rb[8] = {fb0.x, fb0.y, fb0.z, fb0.w, fb1.x, fb1.y, fb1.z, fb1.w};
#pragma unroll
                for (int i = 0; i < 8; i++)
#pragma unroll
                    for (int j = 0; j < 8; j++) acc[i][j] += ra[i] * rb[j];
                if (kk + 1 < BK) { fa0 = na0; fa1 = na1; fb0 = nb0; fb1 = nb1; }
            }
        }
        __syncthreads();
    }

    // Epilogue (same mapping as round 5)
#pragma unroll
    for (int rh = 0; rh < 2; rh++)
#pragma unroll
        for (int i = 0; i < 4; i++) {
            int row = blockIdx.y * 128 + rh * 64 + ty * 4 + i;
            float* zrow = g_z + (size_t)row * DOUT + blockIdx.x * 128;
#pragma unroll
            for (int ch = 0; ch < 2; ch++) {
                float4 v;
                v.x = acc[rh * 4 + i][ch * 4 + 0];
                v.y = acc[rh * 4 + i][ch * 4 + 1];
                v.z = acc[rh * 4 + i][ch * 4 + 2];
                v.w = acc[rh * 4 + i][ch * 4 + 3];
                *reinterpret_cast<float4*>(zrow + ch * 64 + tx * 4) = v;
            }
        }
}

// ---------------------------------------------------------------------------
// Stats: stage-1 verbatim; finalize parallelized (16 CTAs x 32 thr) with
// batched loads. Per-channel add order unchanged (b = 0..255 ascending).
// ---------------------------------------------------------------------------
__global__ __launch_bounds__(256) void reduce_stats_kernel() {
    const int c = threadIdx.x;
    const size_t base = (size_t)blockIdx.x * RED_ROWS * DOUT;
    float s0 = 0.f, q0 = 0.f, s1 = 0.f, q1 = 0.f;
    for (int r = 0; r < RED_ROWS; r++) {
        float z0 = g_z[base + (size_t)r * DOUT + c];
        float z1 = g_z[base + (size_t)r * DOUT + c + 256];
        s0 += z0; q0 += z0 * z0;
        s1 += z1; q1 += z1 * z1;
    }
    g_psum  [blockIdx.x * DOUT + c]       = s0;
    g_psumsq[blockIdx.x * DOUT + c]       = q0;
    g_psum  [blockIdx.x * DOUT + c + 256] = s1;
    g_psumsq[blockIdx.x * DOUT + c + 256] = q1;
}

__global__ void finalize_stats_kernel() {
    const int o = blockIdx.x * 32 + threadIdx.x;   // one channel per thread
    float s = 0.f, q = 0.f;
    for (int b0 = 0; b0 < RED_BLOCKS; b0 += 8) {
        float sv[8], qv[8];
#pragma unroll
        for (int u = 0; u < 8; u++) {
            sv[u] = g_psum  [(b0 + u) * DOUT + o];
            qv[u] = g_psumsq[(b0 + u) * DOUT + o];
        }
#pragma unroll
        for (int u = 0; u < 8; u++) {   // add order: b ascending (bit-identical)
            s += sv[u];
            q += qv[u];
        }
    }
    const float invM = 1.0f / (float)MROWS;
    float mean = s * invM;
    float var = q * invM - mean * mean;
    g_mean[o] = mean;
    g_rstd[o] = 1.0f / sqrtf(var + 1e-5f);
}

// ---------------------------------------------------------------------------
// LIF: verbatim from the passing kernels.
// ---------------------------------------------------------------------------
__global__ __launch_bounds__(256) void lif_kernel(const float* __restrict__ gamma,
                                                  const float* __restrict__ beta,
                                                  float* __restrict__ out) {
    size_t e = ((size_t)blockIdx.x * blockDim.x + threadIdx.x) * 4;
    int o = (int)(e & (DOUT - 1));

    float4 mn4 = *reinterpret_cast<const float4*>(g_mean + o);
    float4 rs4 = *reinterpret_cast<const float4*>(g_rstd + o);
    float4 gm4 = *reinterpret_cast<const float4*>(gamma + o);
    float4 bt4 = *reinterpret_cast<const float4*>(beta + o);
    float mn[4] = {mn4.x, mn4.y, mn4.z, mn4.w};
    float rs[4] = {rs4.x, rs4.y, rs4.z, rs4.w};
    float gm[4] = {gm4.x, gm4.y, gm4.z, gm4.w};
    float bt[4] = {bt4.x, bt4.y, bt4.z, bt4.w};

    float v[4] = {0.f, 0.f, 0.f, 0.f};
#pragma unroll
    for (int t = 0; t < TT; t++) {
        float4 z4 = *reinterpret_cast<const float4*>(g_z + (size_t)t * M3 + e);
        float z[4] = {z4.x, z4.y, z4.z, z4.w};
        float s[4];
#pragma unroll
        for (int l = 0; l < 4; l++) {
            float zn = __fadd_rn(__fmul_rn(__fmul_rn(__fsub_rn(z[l], mn[l]), rs[l]), gm[l]), bt[l]);
            v[l] = __fadd_rn(v[l], __fmul_rn(__fsub_rn(zn, v[l]), 0.5f));
            bool fire = (v[l] >= 1.0f);
            s[l] = fire ? 1.0f : 0.0f;
            v[l] = fire ? 0.0f : v[l];
        }
        *reinterpret_cast<float4*>(out + (size_t)t * M3 + e) = make_float4(s[0], s[1], s[2], s[3]);
    }
}

// ---------------------------------------------------------------------------
extern "C" void kernel_launch(void* const* d_in, const int* in_sizes, int n_in,
                              void* d_out, int out_size) {
    const float* x     = (const float*)d_in[0];
    const float* W     = (const float*)d_in[1];
    const float* gamma = (const float*)d_in[2];
    const float* beta  = (const float*)d_in[3];
    float* out = (float*)d_out;

    dim3 gemm_grid(DOUT / 128, MROWS / 128);     // (4, 512)
    sgemm_kernel<<<gemm_grid, 256>>>(x, W);
    reduce_stats_kernel<<<RED_BLOCKS, 256>>>();
    finalize_stats_kernel<<<16, 32>>>();
    lif_kernel<<<M3 / (256 * 4), 256>>>(gamma, beta, out);
}